// round 9
// baseline (speedup 1.0000x reference)
#include <cuda_runtime.h>
#include <cuda_fp16.h>
#include <stdint.h>

// ---------------------------------------------------------------------------
// EdgeNetwork: messages_e = sum_h H[e,h]*(hw_e @ W2[h]^T) + (hw_e @ b2-tile)
// DECISIVE EXPERIMENT: fp16-accumulator HMMA (m16n8k16.f16) over 4-kt chains,
// upconverted + H-scaled into fp32 twice per step. If legacy fp16-acc is
// double-rate on GB300 -> ~1.6x; if same-rate -> neutral (ALU hidden).
// Main: 148 CTAs x 128 edges, 256 thr, 8 warps m32n64, A register-resident.
// Tail: 66 jobs x 16 edges, 256 thr, 8 warps m16n16.
// ---------------------------------------------------------------------------

#define DD        128
#define EDIM      16
#define EH        128
#define NSTEPS    129
#define STEP_BYTES 32768
#define SLOTS     3
#define TSLOTS    4

// ---- main smem layout ----
#define MB_FULL(i)  ((i)*8)
#define MB_EMPTY(i) (32 + (i)*8)
#define HW_HI       1024
#define HT_OFF      33792
#define W2_OFF      100352
#define SMEM_TOTAL  198656
#define SCR_EF      1024
#define SCR_W1      9216
#define SCR_B1      17408

// ---- tail smem layout ----
#define T_HW       1024
#define T_HT       5120
#define T_W2       13824
#define T_EF       144896
#define T_W1       145920
#define T_B1       154112
#define TAIL_SMEM  154624

static __device__ __align__(128) unsigned char g_w2h[(size_t)NSTEPS * STEP_BYTES];

__device__ __forceinline__ uint32_t s2u(const void* p) {
    return (uint32_t)__cvta_generic_to_shared(p);
}
__device__ __forceinline__ uint32_t swz_chunk(uint32_t c, uint32_t r7) {
    return (c & 8u) | ((c & 7u) ^ r7);
}
__device__ __forceinline__ void mbar_init(uint32_t a, uint32_t cnt) {
    asm volatile("mbarrier.init.shared.b64 [%0], %1;" :: "r"(a), "r"(cnt) : "memory");
}
__device__ __forceinline__ void mbar_expect_tx(uint32_t a, uint32_t bytes) {
    asm volatile("mbarrier.arrive.expect_tx.shared.b64 _, [%0], %1;"
                 :: "r"(a), "r"(bytes) : "memory");
}
__device__ __forceinline__ void mbar_arrive(uint32_t a) {
    asm volatile("mbarrier.arrive.shared.b64 _, [%0];" :: "r"(a) : "memory");
}
__device__ __forceinline__ void mbar_wait(uint32_t a, uint32_t parity) {
    asm volatile(
        "{\n\t.reg .pred P;\n\t"
        "W_%=:\n\t"
        "mbarrier.try_wait.parity.shared.b64 P, [%0], %1;\n\t"
        "@P bra.uni D_%=;\n\t"
        "bra.uni W_%=;\n\t"
        "D_%=:\n\t}"
        :: "r"(a), "r"(parity) : "memory");
}
__device__ __forceinline__ void bulk_g2s(uint32_t dst, const void* src, uint32_t bytes,
                                         uint32_t mbar) {
    asm volatile(
        "cp.async.bulk.shared::cluster.global.mbarrier::complete_tx::bytes [%0], [%1], %2, [%3];"
        :: "r"(dst), "l"(src), "r"(bytes), "r"(mbar) : "memory");
}
__device__ __forceinline__ void ldsm_x4(uint32_t& r0, uint32_t& r1, uint32_t& r2, uint32_t& r3,
                                        uint32_t addr) {
    asm volatile("ldmatrix.sync.aligned.m8n8.x4.shared.b16 {%0,%1,%2,%3}, [%4];"
                 : "=r"(r0), "=r"(r1), "=r"(r2), "=r"(r3) : "r"(addr));
}
// fp16-accumulator MMA: d(2 regs) += a@b
__device__ __forceinline__ void mma16_acc(uint32_t* c, const uint32_t* a,
                                          uint32_t b0, uint32_t b1) {
    asm volatile(
        "mma.sync.aligned.m16n8k16.row.col.f16.f16.f16.f16 "
        "{%0,%1}, {%2,%3,%4,%5}, {%6,%7}, {%0,%1};"
        : "+r"(c[0]), "+r"(c[1])
        : "r"(a[0]), "r"(a[1]), "r"(a[2]), "r"(a[3]), "r"(b0), "r"(b1));
}
__device__ __forceinline__ void mma16_zc(uint32_t* d, const uint32_t* a,
                                         uint32_t b0, uint32_t b1) {
    asm volatile(
        "mma.sync.aligned.m16n8k16.row.col.f16.f16.f16.f16 "
        "{%0,%1}, {%2,%3,%4,%5}, {%6,%7}, {%8,%8};"
        : "=r"(d[0]), "=r"(d[1])
        : "r"(a[0]), "r"(a[1]), "r"(a[2]), "r"(a[3]), "r"(b0), "r"(b1), "r"(0u));
}
// upconvert fp16 d-block and H-scale into fp32 acc
__device__ __forceinline__ void scale_add(float* acc4, const uint32_t* dh,
                                          float hLo, float hHi) {
    float2 lo = __half22float2(*(const __half2*)&dh[0]);
    float2 hi = __half22float2(*(const __half2*)&dh[1]);
    acc4[0] += hLo * lo.x;  acc4[1] += hLo * lo.y;
    acc4[2] += hHi * hi.x;  acc4[3] += hHi * hi.y;
}

// ---------------------------------------------------------------------------
// Prepass: wider grid (129 x 4 small CTAs) for better MLP/occupancy.
// ---------------------------------------------------------------------------
__global__ void __launch_bounds__(128) w2_prepass(const float* __restrict__ W2,
                                                  const float* __restrict__ b2) {
    const int h = blockIdx.x;
    const int q = blockIdx.y;
    const int tid = threadIdx.x;
    const float* src = (h < EH) ? (W2 + (size_t)h * (DD * DD)) : b2;
    unsigned char* dst = g_w2h + (size_t)h * STEP_BYTES;
    #pragma unroll
    for (int it = 0; it < 4; ++it) {
        int cid = q * 512 + it * 128 + tid;   // 2048 chunks of 8 halves total
        int i = cid >> 4;
        int c = cid & 15;
        const float* s = src + (size_t)i * DD + c * 8;
        float4 a = *(const float4*)s;
        float4 b = *(const float4*)(s + 4);
        __half2 h0 = __floats2half2_rn(a.x, a.y);
        __half2 h1 = __floats2half2_rn(a.z, a.w);
        __half2 h2 = __floats2half2_rn(b.x, b.y);
        __half2 h3 = __floats2half2_rn(b.z, b.w);
        uint32_t off = (uint32_t)i * 256u + (swz_chunk((uint32_t)c, (uint32_t)(i & 7)) << 4);
        uint4 v;
        v.x = *(uint32_t*)&h0; v.y = *(uint32_t*)&h1;
        v.z = *(uint32_t*)&h2; v.w = *(uint32_t*)&h3;
        *(uint4*)(dst + off) = v;
    }
}

// ---------------------------------------------------------------------------
// Main: 128 edges/CTA, 256 threads, 8 warps 4(M)x2(N) -> m32 x n64
// ---------------------------------------------------------------------------
__global__ void __launch_bounds__(256, 1)
edge_main(const float* __restrict__ hw, const float* __restrict__ ef,
          const float* __restrict__ W1, const float* __restrict__ b1,
          float* __restrict__ out, int n) {
    extern __shared__ __align__(1024) unsigned char smem[];
    const uint32_t smem_b = s2u(smem);
    const int tid = threadIdx.x;
    const int lane = tid & 31;
    const int wid = tid >> 5;
    const int warp_m = wid & 3;
    const int warp_n = wid >> 2;
    const int e0 = blockIdx.x * 128;

    if (tid == 0) {
        #pragma unroll
        for (int i = 0; i < SLOTS; ++i) {
            mbar_init(smem_b + MB_FULL(i), 1);
            mbar_init(smem_b + MB_EMPTY(i), 8);
        }
        asm volatile("fence.mbarrier_init.release.cluster;" ::: "memory");
    }
    __syncthreads();
    if (tid == 0) {
        #pragma unroll
        for (int i = 0; i < SLOTS; ++i) {
            mbar_expect_tx(smem_b + MB_FULL(i), STEP_BYTES);
            bulk_g2s(smem_b + W2_OFF + i * STEP_BYTES, g_w2h + (size_t)i * STEP_BYTES,
                     STEP_BYTES, smem_b + MB_FULL(i));
        }
    }

    // -------- stage ef / W1 / b1 --------
    {
        float* ef_s = (float*)(smem + SCR_EF);
        float* w1_s = (float*)(smem + SCR_W1);
        float* b1_s = (float*)(smem + SCR_B1);
        ((float4*)ef_s)[tid] = ((const float4*)(ef + (size_t)e0 * EDIM))[tid];
        ((float4*)ef_s)[tid + 256] = ((const float4*)(ef + (size_t)e0 * EDIM))[tid + 256];
        ((float4*)w1_s)[tid] = ((const float4*)W1)[tid];
        ((float4*)w1_s)[tid + 256] = ((const float4*)W1)[tid + 256];
        if (tid < EH) b1_s[tid] = b1[tid];
    }
    __syncthreads();

    // -------- MLP: Ht[h][e] fp32, step 128 = 1.0 --------
    {
        const float* ef_s = (const float*)(smem + SCR_EF);
        const float* w1_s = (const float*)(smem + SCR_W1);
        const float* b1_s = (const float*)(smem + SCR_B1);
        float* ht = (float*)(smem + HT_OFF);
        const int e = tid >> 1;
        const int part = tid & 1;
        float efr[EDIM];
        #pragma unroll
        for (int k = 0; k < EDIM; ++k) efr[k] = ef_s[e * EDIM + k];
        const int h0 = part * 64;
        #pragma unroll 4
        for (int hh = 0; hh < 64; hh += 4) {
            float4 acc4 = *(const float4*)(b1_s + h0 + hh);
            #pragma unroll
            for (int k = 0; k < EDIM; ++k) {
                float4 w = *(const float4*)(w1_s + k * EH + h0 + hh);
                acc4.x += efr[k] * w.x; acc4.y += efr[k] * w.y;
                acc4.z += efr[k] * w.z; acc4.w += efr[k] * w.w;
            }
            ht[(h0 + hh + 0) * 128 + e] = fmaxf(acc4.x, 0.f);
            ht[(h0 + hh + 1) * 128 + e] = fmaxf(acc4.y, 0.f);
            ht[(h0 + hh + 2) * 128 + e] = fmaxf(acc4.z, 0.f);
            ht[(h0 + hh + 3) * 128 + e] = fmaxf(acc4.w, 0.f);
        }
        if (part == 0) ht[128 * 128 + e] = 1.0f;
    }
    __syncthreads();

    // -------- hw fp16 image --------
    {
        #pragma unroll
        for (int q = 0; q < 8; ++q) {
            int cid = tid + q * 256;
            int r = cid >> 4;
            int c = cid & 15;
            const float* s = hw + (size_t)(e0 + r) * DD + c * 8;
            float4 a = *(const float4*)s;
            float4 b = *(const float4*)(s + 4);
            __half2 h0 = __floats2half2_rn(a.x, a.y);
            __half2 h1 = __floats2half2_rn(a.z, a.w);
            __half2 h2 = __floats2half2_rn(b.x, b.y);
            __half2 h3 = __floats2half2_rn(b.z, b.w);
            uint32_t off = (uint32_t)r * 256u + (swz_chunk((uint32_t)c, (uint32_t)(r & 7)) << 4);
            uint4 v;
            v.x = *(uint32_t*)&h0; v.y = *(uint32_t*)&h1;
            v.z = *(uint32_t*)&h2; v.w = *(uint32_t*)&h3;
            *(uint4*)(smem + HW_HI + off) = v;
        }
    }
    __syncthreads();

    // -------- A fragments into registers (step-invariant) --------
    const uint32_t rx = (uint32_t)(lane & 7);
    const uint32_t lhi = (uint32_t)(lane >> 4);
    uint32_t coffv[8];
    #pragma unroll
    for (int kt = 0; kt < 8; ++kt)
        coffv[kt] = swz_chunk((uint32_t)(kt * 2) + lhi, rx) << 4;

    uint32_t A0[8][4], A1[8][4];
    {
        const uint32_t aBase0 = smem_b + HW_HI + (uint32_t)(warp_m * 32 + (lane & 15)) * 256u;
        const uint32_t aBase1 = aBase0 + 16u * 256u;
        #pragma unroll
        for (int kt = 0; kt < 8; ++kt) {
            ldsm_x4(A0[kt][0], A0[kt][1], A0[kt][2], A0[kt][3], aBase0 + coffv[kt]);
            ldsm_x4(A1[kt][0], A1[kt][1], A1[kt][2], A1[kt][3], aBase1 + coffv[kt]);
        }
    }

    uint32_t bR[4];
    #pragma unroll
    for (int g = 0; g < 4; ++g)
        bR[g] = (uint32_t)(warp_n * 64 + g * 16 + (lane & 15)) * 256u;

    const float* ht = (const float*)(smem + HT_OFF);
    const int quad = lane >> 2;
    const int hrow = warp_m * 32 + quad;

    float acc[2][8][4];
    #pragma unroll
    for (int mf = 0; mf < 2; ++mf)
        #pragma unroll
        for (int f = 0; f < 8; ++f)
            #pragma unroll
            for (int q = 0; q < 4; ++q) acc[mf][f][q] = 0.f;

    // -------- main loop --------
    int slot = 0, use = 0;
    for (int s = 0; s < NSTEPS; ++s) {
        const uint32_t par = (uint32_t)use & 1u;
        mbar_wait(smem_b + MB_FULL(slot), par);

        const float hA0 = ht[s * 128 + hrow];
        const float hB0 = ht[s * 128 + hrow + 8];
        const float hA1 = ht[s * 128 + hrow + 16];
        const float hB1 = ht[s * 128 + hrow + 24];
        const uint32_t bSlot = smem_b + W2_OFF + slot * STEP_BYTES;

        // two 4-kt fp16-accumulate chains; upconvert+scale after each
        #pragma unroll
        for (int half = 0; half < 2; ++half) {
            uint32_t dh[16][2];   // [mf*8 + g*2 + b][2]
            #pragma unroll
            for (int kk = 0; kk < 4; ++kk) {
                const int kt = half * 4 + kk;
                #pragma unroll
                for (int g = 0; g < 4; ++g) {
                    uint32_t b0, b1r, b2, b3;
                    ldsm_x4(b0, b1r, b2, b3, bSlot + bR[g] + coffv[kt]);
                    if (kk == 0) {
                        mma16_zc(dh[g * 2 + 0], A0[kt], b0, b2);
                        mma16_zc(dh[g * 2 + 1], A0[kt], b1r, b3);
                        mma16_zc(dh[8 + g * 2 + 0], A1[kt], b0, b2);
                        mma16_zc(dh[8 + g * 2 + 1], A1[kt], b1r, b3);
                    } else {
                        mma16_acc(dh[g * 2 + 0], A0[kt], b0, b2);
                        mma16_acc(dh[g * 2 + 1], A0[kt], b1r, b3);
                        mma16_acc(dh[8 + g * 2 + 0], A1[kt], b0, b2);
                        mma16_acc(dh[8 + g * 2 + 1], A1[kt], b1r, b3);
                    }
                }
            }
            #pragma unroll
            for (int j = 0; j < 8; ++j) {
                scale_add(acc[0][j], dh[j], hA0, hB0);
                scale_add(acc[1][j], dh[8 + j], hA1, hB1);
            }
        }
        __syncwarp();
        if (lane == 0) mbar_arrive(smem_b + MB_EMPTY(slot));

        if (tid == 0 && s + SLOTS < NSTEPS) {
            mbar_wait(smem_b + MB_EMPTY(slot), par);
            mbar_expect_tx(smem_b + MB_FULL(slot), STEP_BYTES);
            bulk_g2s(smem_b + W2_OFF + slot * STEP_BYTES,
                     g_w2h + (size_t)(s + SLOTS) * STEP_BYTES, STEP_BYTES,
                     smem_b + MB_FULL(slot));
        }
        if (++slot == SLOTS) { slot = 0; ++use; }
    }

    // -------- epilogue --------
    #pragma unroll
    for (int mf = 0; mf < 2; ++mf) {
        const int er = e0 + warp_m * 32 + mf * 16 + quad;
        #pragma unroll
        for (int gg = 0; gg < 4; ++gg)
            #pragma unroll
            for (int b = 0; b < 2; ++b) {
                const int f = gg * 2 + b;
                const int col = warp_n * 64 + gg * 16 + b * 8 + (lane & 3) * 2;
                *(float2*)(out + (size_t)er * DD + col) =
                    make_float2(acc[mf][f][0], acc[mf][f][1]);
                *(float2*)(out + (size_t)(er + 8) * DD + col) =
                    make_float2(acc[mf][f][2], acc[mf][f][3]);
            }
    }
}

// ---------------------------------------------------------------------------
// Tail: 16 edges/CTA, 256 threads, 8 warps m16n16, 4 slots, fp16 chains.
// ---------------------------------------------------------------------------
__global__ void __launch_bounds__(256, 1)
edge_tail(const float* __restrict__ hw, const float* __restrict__ ef,
          const float* __restrict__ W1, const float* __restrict__ b1,
          float* __restrict__ out, int n, int e_base) {
    extern __shared__ __align__(1024) unsigned char smem[];
    const uint32_t smem_b = s2u(smem);
    const int tid = threadIdx.x;
    const int lane = tid & 31;
    const int wid = tid >> 5;
    const int e0 = e_base + blockIdx.x * 16;

    if (tid == 0) {
        #pragma unroll
        for (int i = 0; i < TSLOTS; ++i) {
            mbar_init(smem_b + MB_FULL(i), 1);
            mbar_init(smem_b + MB_EMPTY(i), 8);
        }
        asm volatile("fence.mbarrier_init.release.cluster;" ::: "memory");
    }
    __syncthreads();
    if (tid == 0) {
        #pragma unroll
        for (int i = 0; i < TSLOTS; ++i) {
            mbar_expect_tx(smem_b + MB_FULL(i), STEP_BYTES);
            bulk_g2s(smem_b + T_W2 + i * STEP_BYTES, g_w2h + (size_t)i * STEP_BYTES,
                     STEP_BYTES, smem_b + MB_FULL(i));
        }
    }

    {
        float* ef_s = (float*)(smem + T_EF);
        float* w1_s = (float*)(smem + T_W1);
        float* b1_s = (float*)(smem + T_B1);
        if (tid < 64) {
            int e = tid >> 2;
            float4 v = make_float4(0.f, 0.f, 0.f, 0.f);
            if (e0 + e < n) v = *(const float4*)(ef + (size_t)(e0 + e) * EDIM + (tid & 3) * 4);
            ((float4*)ef_s)[tid] = v;
        }
        ((float4*)w1_s)[tid] = ((const float4*)W1)[tid];
        ((float4*)w1_s)[tid + 256] = ((const float4*)W1)[tid + 256];
        if (tid < EH) b1_s[tid] = b1[tid];
    }
    __syncthreads();

    {
        const float* ef_s = (const float*)(smem + T_EF);
        const float* w1_s = (const float*)(smem + T_W1);
        const float* b1_s = (const float*)(smem + T_B1);
        float* ht = (float*)(smem + T_HT);
        const int e = tid >> 4;
        const int part = tid & 15;
        float efr[EDIM];
        #pragma unroll
        for (int k = 0; k < EDIM; ++k) efr[k] = ef_s[e * EDIM + k];
        const int h0 = part * 8;
        #pragma unroll
        for (int hh = 0; hh < 8; hh += 4) {
            float4 acc4 = *(const float4*)(b1_s + h0 + hh);
            #pragma unroll
            for (int k = 0; k < EDIM; ++k) {
                float4 w = *(const float4*)(w1_s + k * EH + h0 + hh);
                acc4.x += efr[k] * w.x; acc4.y += efr[k] * w.y;
                acc4.z += efr[k] * w.z; acc4.w += efr[k] * w.w;
            }
            ht[(h0 + hh + 0) * 16 + e] = fmaxf(acc4.x, 0.f);
            ht[(h0 + hh + 1) * 16 + e] = fmaxf(acc4.y, 0.f);
            ht[(h0 + hh + 2) * 16 + e] = fmaxf(acc4.z, 0.f);
            ht[(h0 + hh + 3) * 16 + e] = fmaxf(acc4.w, 0.f);
        }
        if (part == 0) ht[128 * 16 + e] = 1.0f;
    }
    __syncthreads();

    {
        int r = tid >> 4;
        int c = tid & 15;
        float4 a = make_float4(0.f, 0.f, 0.f, 0.f), b = a;
        if (e0 + r < n) {
            const float* s = hw + (size_t)(e0 + r) * DD + c * 8;
            a = *(const float4*)s;
            b = *(const float4*)(s + 4);
        }
        __half2 h0 = __floats2half2_rn(a.x, a.y);
        __half2 h1 = __floats2half2_rn(a.z, a.w);
        __half2 h2 = __floats2half2_rn(b.x, b.y);
        __half2 h3 = __floats2half2_rn(b.z, b.w);
        uint32_t off = (uint32_t)r * 256u + (swz_chunk((uint32_t)c, (uint32_t)(r & 7)) << 4);
        uint4 v;
        v.x = *(uint32_t*)&h0; v.y = *(uint32_t*)&h1;
        v.z = *(uint32_t*)&h2; v.w = *(uint32_t*)&h3;
        *(uint4*)(smem + T_HW + off) = v;
    }
    __syncthreads();

    const uint32_t rx = (uint32_t)(lane & 7);
    const uint32_t lhi = (uint32_t)(lane >> 4);
    uint32_t coffv[8];
    #pragma unroll
    for (int kt = 0; kt < 8; ++kt)
        coffv[kt] = swz_chunk((uint32_t)(kt * 2) + lhi, rx) << 4;

    uint32_t A[8][4];
    {
        const uint32_t aBase = smem_b + T_HW + (uint32_t)(lane & 15) * 256u;
        #pragma unroll
        for (int kt = 0; kt < 8; ++kt)
            ldsm_x4(A[kt][0], A[kt][1], A[kt][2], A[kt][3], aBase + coffv[kt]);
    }
    const uint32_t bRow = (uint32_t)(wid * 16 + (lane & 15)) * 256u;
    const float* ht = (const float*)(smem + T_HT);
    const int quad = lane >> 2;

    float acc[2][4];
    #pragma unroll
    for (int f = 0; f < 2; ++f)
        #pragma unroll
        for (int q = 0; q < 4; ++q) acc[f][q] = 0.f;

    int slot = 0, use = 0;
    for (int s = 0; s < NSTEPS; ++s) {
        const uint32_t par = (uint32_t)use & 1u;
        mbar_wait(smem_b + MB_FULL(slot), par);

        const float hA = ht[s * 16 + quad];
        const float hB = ht[s * 16 + quad + 8];
        const uint32_t bSlot = smem_b + T_W2 + slot * STEP_BYTES;

        #pragma unroll
        for (int half = 0; half < 2; ++half) {
            uint32_t dh[2][2];
            #pragma unroll
            for (int kk = 0; kk < 4; ++kk) {
                const int kt = half * 4 + kk;
                uint32_t b0, b1r, b2, b3;
                ldsm_x4(b0, b1r, b2, b3, bSlot + bRow + coffv[kt]);
                if (kk == 0) {
                    mma16_zc(dh[0], A[kt], b0, b2);
                    mma16_zc(dh[1], A[kt], b1r, b3);
                } else {
                    mma16_acc(dh[0], A[kt], b0, b2);
                    mma16_acc(dh[1], A[kt], b1r, b3);
                }
            }
            scale_add(acc[0], dh[0], hA, hB);
            scale_add(acc[1], dh[1], hA, hB);
        }
        __syncwarp();
        if (lane == 0) mbar_arrive(smem_b + MB_EMPTY(slot));

        if (tid == 0 && s + TSLOTS < NSTEPS) {
            mbar_wait(smem_b + MB_EMPTY(slot), par);
            mbar_expect_tx(smem_b + MB_FULL(slot), STEP_BYTES);
            bulk_g2s(smem_b + T_W2 + slot * STEP_BYTES,
                     g_w2h + (size_t)(s + TSLOTS) * STEP_BYTES, STEP_BYTES,
                     smem_b + MB_FULL(slot));
        }
        if (++slot == TSLOTS) { slot = 0; ++use; }
    }

    const int er = e0 + quad;
    #pragma unroll
    for (int b = 0; b < 2; ++b) {
        const int col = wid * 16 + b * 8 + (lane & 3) * 2;
        if (er < n)
            *(float2*)(out + (size_t)er * DD + col) = make_float2(acc[b][0], acc[b][1]);
        if (er + 8 < n)
            *(float2*)(out + (size_t)(er + 8) * DD + col) = make_float2(acc[b][2], acc[b][3]);
    }
}

// ---------------------------------------------------------------------------
extern "C" void kernel_launch(void* const* d_in, const int* in_sizes, int n_in,
                              void* d_out, int out_size) {
    const float* hw = (const float*)d_in[1];
    const float* ef = (const float*)d_in[2];
    const float* W1 = (const float*)d_in[3];
    const float* b1 = (const float*)d_in[4];
    const float* W2 = (const float*)d_in[5];
    const float* b2 = (const float*)d_in[6];
    const int n = in_sizes[1] / DD;

    w2_prepass<<<dim3(NSTEPS, 4), 128>>>(W2, b2);

    int full = n / 128;
    if (full > 148) full = 148;
    const int rem = n - full * 128;
    const int jobs = (rem + 15) / 16;
    if (jobs > 0) {
        cudaFuncSetAttribute(edge_tail, cudaFuncAttributeMaxDynamicSharedMemorySize,
                             TAIL_SMEM);
        edge_tail<<<jobs, 256, TAIL_SMEM>>>(hw, ef, W1, b1, (float*)d_out, n, full * 128);
    }
    if (full > 0) {
        cudaFuncSetAttribute(edge_main, cudaFuncAttributeMaxDynamicSharedMemorySize,
                             SMEM_TOTAL);
        edge_main<<<full, 256, SMEM_TOTAL>>>(hw, ef, W1, b1, (float*)d_out, n);
    }
}

// round 10
// speedup vs baseline: 1.0948x; 1.0948x over previous
#include <cuda_runtime.h>
#include <cuda_fp16.h>
#include <stdint.h>

// ---------------------------------------------------------------------------
// EdgeNetwork: messages_e = sum_h H[e,h]*(hw_e @ W2[h]^T) + (hw_e @ b2-tile)
// H applied POST-MMA in fp32. A (= hw) fragments register-resident.
// Main (R8 config, at legacy-HMMA ceiling): 148 CTAs x 128 edges, 256 thr,
// 8 warps m32n64, d[16][4] single pass.
// Tail: 66 jobs x 16 edges, 512 thr, 16 warps = (8 n16-groups) x (2 k-halves);
// per-warp fp32 partial accs, combined once in epilogue via smem.
// ---------------------------------------------------------------------------

#define DD        128
#define EDIM      16
#define EH        128
#define NSTEPS    129
#define STEP_BYTES 32768
#define SLOTS     3
#define TSLOTS    4

// ---- main smem layout ----
#define MB_FULL(i)  ((i)*8)
#define MB_EMPTY(i) (32 + (i)*8)
#define HW_HI       1024
#define HT_OFF      33792
#define W2_OFF      100352
#define SMEM_TOTAL  198656
#define SCR_EF      1024
#define SCR_W1      9216
#define SCR_B1      17408

// ---- tail smem layout ----
#define T_HW       1024                  // 16 x 256B = 4096
#define T_HT       5120                  // 129*16*4 = 8256 (combine buf reuses this)
#define T_W2       13824                 // 4 x 32768 -> 144896
#define T_EF       144896
#define T_W1       145920
#define T_B1       154112
#define TAIL_SMEM  154624

static __device__ __align__(128) unsigned char g_w2h[(size_t)NSTEPS * STEP_BYTES];

__device__ __forceinline__ uint32_t s2u(const void* p) {
    return (uint32_t)__cvta_generic_to_shared(p);
}
__device__ __forceinline__ uint32_t swz_chunk(uint32_t c, uint32_t r7) {
    return (c & 8u) | ((c & 7u) ^ r7);
}
__device__ __forceinline__ void mbar_init(uint32_t a, uint32_t cnt) {
    asm volatile("mbarrier.init.shared.b64 [%0], %1;" :: "r"(a), "r"(cnt) : "memory");
}
__device__ __forceinline__ void mbar_expect_tx(uint32_t a, uint32_t bytes) {
    asm volatile("mbarrier.arrive.expect_tx.shared.b64 _, [%0], %1;"
                 :: "r"(a), "r"(bytes) : "memory");
}
__device__ __forceinline__ void mbar_arrive(uint32_t a) {
    asm volatile("mbarrier.arrive.shared.b64 _, [%0];" :: "r"(a) : "memory");
}
__device__ __forceinline__ void mbar_wait(uint32_t a, uint32_t parity) {
    asm volatile(
        "{\n\t.reg .pred P;\n\t"
        "W_%=:\n\t"
        "mbarrier.try_wait.parity.shared.b64 P, [%0], %1;\n\t"
        "@P bra.uni D_%=;\n\t"
        "bra.uni W_%=;\n\t"
        "D_%=:\n\t}"
        :: "r"(a), "r"(parity) : "memory");
}
__device__ __forceinline__ void bulk_g2s(uint32_t dst, const void* src, uint32_t bytes,
                                         uint32_t mbar) {
    asm volatile(
        "cp.async.bulk.shared::cluster.global.mbarrier::complete_tx::bytes [%0], [%1], %2, [%3];"
        :: "r"(dst), "l"(src), "r"(bytes), "r"(mbar) : "memory");
}
__device__ __forceinline__ void ldsm_x4(uint32_t& r0, uint32_t& r1, uint32_t& r2, uint32_t& r3,
                                        uint32_t addr) {
    asm volatile("ldmatrix.sync.aligned.m8n8.x4.shared.b16 {%0,%1,%2,%3}, [%4];"
                 : "=r"(r0), "=r"(r1), "=r"(r2), "=r"(r3) : "r"(addr));
}
__device__ __forceinline__ void mma_acc(float* c, const uint32_t* a,
                                        uint32_t b0, uint32_t b1) {
    asm volatile(
        "mma.sync.aligned.m16n8k16.row.col.f32.f16.f16.f32 "
        "{%0,%1,%2,%3}, {%4,%5,%6,%7}, {%8,%9}, {%0,%1,%2,%3};"
        : "+f"(c[0]), "+f"(c[1]), "+f"(c[2]), "+f"(c[3])
        : "r"(a[0]), "r"(a[1]), "r"(a[2]), "r"(a[3]), "r"(b0), "r"(b1));
}
__device__ __forceinline__ void mma_zc(float* d, const uint32_t* a,
                                       uint32_t b0, uint32_t b1) {
    asm volatile(
        "mma.sync.aligned.m16n8k16.row.col.f32.f16.f16.f32 "
        "{%0,%1,%2,%3}, {%4,%5,%6,%7}, {%8,%9}, {%10,%11,%12,%13};"
        : "=f"(d[0]), "=f"(d[1]), "=f"(d[2]), "=f"(d[3])
        : "r"(a[0]), "r"(a[1]), "r"(a[2]), "r"(a[3]), "r"(b0), "r"(b1),
          "f"(0.f), "f"(0.f), "f"(0.f), "f"(0.f));
}

// ---------------------------------------------------------------------------
__global__ void __launch_bounds__(128) w2_prepass(const float* __restrict__ W2,
                                                  const float* __restrict__ b2) {
    const int h = blockIdx.x;
    const int q = blockIdx.y;
    const int tid = threadIdx.x;
    const float* src = (h < EH) ? (W2 + (size_t)h * (DD * DD)) : b2;
    unsigned char* dst = g_w2h + (size_t)h * STEP_BYTES;
    #pragma unroll
    for (int it = 0; it < 4; ++it) {
        int cid = q * 512 + it * 128 + tid;
        int i = cid >> 4;
        int c = cid & 15;
        const float* s = src + (size_t)i * DD + c * 8;
        float4 a = *(const float4*)s;
        float4 b = *(const float4*)(s + 4);
        __half2 h0 = __floats2half2_rn(a.x, a.y);
        __half2 h1 = __floats2half2_rn(a.z, a.w);
        __half2 h2 = __floats2half2_rn(b.x, b.y);
        __half2 h3 = __floats2half2_rn(b.z, b.w);
        uint32_t off = (uint32_t)i * 256u + (swz_chunk((uint32_t)c, (uint32_t)(i & 7)) << 4);
        uint4 v;
        v.x = *(uint32_t*)&h0; v.y = *(uint32_t*)&h1;
        v.z = *(uint32_t*)&h2; v.w = *(uint32_t*)&h3;
        *(uint4*)(dst + off) = v;
    }
}

// ---------------------------------------------------------------------------
// Main: 128 edges/CTA, 256 threads, 8 warps 4(M)x2(N) -> m32 x n64 (R8 config)
// ---------------------------------------------------------------------------
__global__ void __launch_bounds__(256, 1)
edge_main(const float* __restrict__ hw, const float* __restrict__ ef,
          const float* __restrict__ W1, const float* __restrict__ b1,
          float* __restrict__ out, int n) {
    extern __shared__ __align__(1024) unsigned char smem[];
    const uint32_t smem_b = s2u(smem);
    const int tid = threadIdx.x;
    const int lane = tid & 31;
    const int wid = tid >> 5;
    const int warp_m = wid & 3;
    const int warp_n = wid >> 2;
    const int e0 = blockIdx.x * 128;

    if (tid == 0) {
        #pragma unroll
        for (int i = 0; i < SLOTS; ++i) {
            mbar_init(smem_b + MB_FULL(i), 1);
            mbar_init(smem_b + MB_EMPTY(i), 8);
        }
        asm volatile("fence.mbarrier_init.release.cluster;" ::: "memory");
    }
    __syncthreads();
    if (tid == 0) {
        #pragma unroll
        for (int i = 0; i < SLOTS; ++i) {
            mbar_expect_tx(smem_b + MB_FULL(i), STEP_BYTES);
            bulk_g2s(smem_b + W2_OFF + i * STEP_BYTES, g_w2h + (size_t)i * STEP_BYTES,
                     STEP_BYTES, smem_b + MB_FULL(i));
        }
    }

    // -------- stage ef / W1 / b1 --------
    {
        float* ef_s = (float*)(smem + SCR_EF);
        float* w1_s = (float*)(smem + SCR_W1);
        float* b1_s = (float*)(smem + SCR_B1);
        ((float4*)ef_s)[tid] = ((const float4*)(ef + (size_t)e0 * EDIM))[tid];
        ((float4*)ef_s)[tid + 256] = ((const float4*)(ef + (size_t)e0 * EDIM))[tid + 256];
        ((float4*)w1_s)[tid] = ((const float4*)W1)[tid];
        ((float4*)w1_s)[tid + 256] = ((const float4*)W1)[tid + 256];
        if (tid < EH) b1_s[tid] = b1[tid];
    }
    __syncthreads();

    // -------- MLP: Ht[h][e] fp32, step 128 = 1.0 --------
    {
        const float* ef_s = (const float*)(smem + SCR_EF);
        const float* w1_s = (const float*)(smem + SCR_W1);
        const float* b1_s = (const float*)(smem + SCR_B1);
        float* ht = (float*)(smem + HT_OFF);
        const int e = tid >> 1;
        const int part = tid & 1;
        float efr[EDIM];
        #pragma unroll
        for (int k = 0; k < EDIM; ++k) efr[k] = ef_s[e * EDIM + k];
        const int h0 = part * 64;
        #pragma unroll 4
        for (int hh = 0; hh < 64; hh += 4) {
            float4 acc4 = *(const float4*)(b1_s + h0 + hh);
            #pragma unroll
            for (int k = 0; k < EDIM; ++k) {
                float4 w = *(const float4*)(w1_s + k * EH + h0 + hh);
                acc4.x += efr[k] * w.x; acc4.y += efr[k] * w.y;
                acc4.z += efr[k] * w.z; acc4.w += efr[k] * w.w;
            }
            ht[(h0 + hh + 0) * 128 + e] = fmaxf(acc4.x, 0.f);
            ht[(h0 + hh + 1) * 128 + e] = fmaxf(acc4.y, 0.f);
            ht[(h0 + hh + 2) * 128 + e] = fmaxf(acc4.z, 0.f);
            ht[(h0 + hh + 3) * 128 + e] = fmaxf(acc4.w, 0.f);
        }
        if (part == 0) ht[128 * 128 + e] = 1.0f;
    }
    __syncthreads();

    // -------- hw fp16 image --------
    {
        #pragma unroll
        for (int q = 0; q < 8; ++q) {
            int cid = tid + q * 256;
            int r = cid >> 4;
            int c = cid & 15;
            const float* s = hw + (size_t)(e0 + r) * DD + c * 8;
            float4 a = *(const float4*)s;
            float4 b = *(const float4*)(s + 4);
            __half2 h0 = __floats2half2_rn(a.x, a.y);
            __half2 h1 = __floats2half2_rn(a.z, a.w);
            __half2 h2 = __floats2half2_rn(b.x, b.y);
            __half2 h3 = __floats2half2_rn(b.z, b.w);
            uint32_t off = (uint32_t)r * 256u + (swz_chunk((uint32_t)c, (uint32_t)(r & 7)) << 4);
            uint4 v;
            v.x = *(uint32_t*)&h0; v.y = *(uint32_t*)&h1;
            v.z = *(uint32_t*)&h2; v.w = *(uint32_t*)&h3;
            *(uint4*)(smem + HW_HI + off) = v;
        }
    }
    __syncthreads();

    // -------- A fragments into registers (step-invariant) --------
    const uint32_t rx = (uint32_t)(lane & 7);
    const uint32_t lhi = (uint32_t)(lane >> 4);
    uint32_t coffv[8];
    #pragma unroll
    for (int kt = 0; kt < 8; ++kt)
        coffv[kt] = swz_chunk((uint32_t)(kt * 2) + lhi, rx) << 4;

    uint32_t A0[8][4], A1[8][4];
    {
        const uint32_t aBase0 = smem_b + HW_HI + (uint32_t)(warp_m * 32 + (lane & 15)) * 256u;
        const uint32_t aBase1 = aBase0 + 16u * 256u;
        #pragma unroll
        for (int kt = 0; kt < 8; ++kt) {
            ldsm_x4(A0[kt][0], A0[kt][1], A0[kt][2], A0[kt][3], aBase0 + coffv[kt]);
            ldsm_x4(A1[kt][0], A1[kt][1], A1[kt][2], A1[kt][3], aBase1 + coffv[kt]);
        }
    }

    uint32_t bR[4];
    #pragma unroll
    for (int g = 0; g < 4; ++g)
        bR[g] = (uint32_t)(warp_n * 64 + g * 16 + (lane & 15)) * 256u;

    const float* ht = (const float*)(smem + HT_OFF);
    const int quad = lane >> 2;
    const int hrow = warp_m * 32 + quad;

    float acc[2][8][4];
    #pragma unroll
    for (int mf = 0; mf < 2; ++mf)
        #pragma unroll
        for (int f = 0; f < 8; ++f)
            #pragma unroll
            for (int q = 0; q < 4; ++q) acc[mf][f][q] = 0.f;

    // -------- main loop --------
    int slot = 0, use = 0;
    for (int s = 0; s < NSTEPS; ++s) {
        const uint32_t par = (uint32_t)use & 1u;
        mbar_wait(smem_b + MB_FULL(slot), par);

        const float hA0 = ht[s * 128 + hrow];
        const float hB0 = ht[s * 128 + hrow + 8];
        const float hA1 = ht[s * 128 + hrow + 16];
        const float hB1 = ht[s * 128 + hrow + 24];
        const uint32_t bSlot = smem_b + W2_OFF + slot * STEP_BYTES;

        float d[16][4];
        #pragma unroll
        for (int kt = 0; kt < 8; ++kt) {
            #pragma unroll
            for (int g = 0; g < 4; ++g) {
                uint32_t b0, b1r, b2, b3;
                ldsm_x4(b0, b1r, b2, b3, bSlot + bR[g] + coffv[kt]);
                if (kt == 0) {
                    mma_zc(d[g * 2 + 0], A0[0], b0, b2);
                    mma_zc(d[g * 2 + 1], A0[0], b1r, b3);
                    mma_zc(d[8 + g * 2 + 0], A1[0], b0, b2);
                    mma_zc(d[8 + g * 2 + 1], A1[0], b1r, b3);
                } else {
                    mma_acc(d[g * 2 + 0], A0[kt], b0, b2);
                    mma_acc(d[g * 2 + 1], A0[kt], b1r, b3);
                    mma_acc(d[8 + g * 2 + 0], A1[kt], b0, b2);
                    mma_acc(d[8 + g * 2 + 1], A1[kt], b1r, b3);
                }
            }
        }
        __syncwarp();
        if (lane == 0) mbar_arrive(smem_b + MB_EMPTY(slot));

        #pragma unroll
        for (int j = 0; j < 8; ++j) {
            float* a0 = acc[0][j];
            float* a1 = acc[1][j];
            a0[0] += hA0 * d[j][0];      a0[1] += hA0 * d[j][1];
            a0[2] += hB0 * d[j][2];      a0[3] += hB0 * d[j][3];
            a1[0] += hA1 * d[8 + j][0];  a1[1] += hA1 * d[8 + j][1];
            a1[2] += hB1 * d[8 + j][2];  a1[3] += hB1 * d[8 + j][3];
        }

        if (tid == 0 && s + SLOTS < NSTEPS) {
            mbar_wait(smem_b + MB_EMPTY(slot), par);
            mbar_expect_tx(smem_b + MB_FULL(slot), STEP_BYTES);
            bulk_g2s(smem_b + W2_OFF + slot * STEP_BYTES,
                     g_w2h + (size_t)(s + SLOTS) * STEP_BYTES, STEP_BYTES,
                     smem_b + MB_FULL(slot));
        }
        if (++slot == SLOTS) { slot = 0; ++use; }
    }

    // -------- epilogue --------
    #pragma unroll
    for (int mf = 0; mf < 2; ++mf) {
        const int er = e0 + warp_m * 32 + mf * 16 + quad;
        #pragma unroll
        for (int gg = 0; gg < 4; ++gg)
            #pragma unroll
            for (int b = 0; b < 2; ++b) {
                const int f = gg * 2 + b;
                const int col = warp_n * 64 + gg * 16 + b * 8 + (lane & 3) * 2;
                *(float2*)(out + (size_t)er * DD + col) =
                    make_float2(acc[mf][f][0], acc[mf][f][1]);
                *(float2*)(out + (size_t)(er + 8) * DD + col) =
                    make_float2(acc[mf][f][2], acc[mf][f][3]);
            }
    }
}

// ---------------------------------------------------------------------------
// Tail: 16 edges/CTA, 512 threads, 16 warps = (8 n16-groups) x (2 k-halves).
// Each warp accumulates its k-half partial in fp32; combined once at the end.
// ---------------------------------------------------------------------------
__global__ void __launch_bounds__(512, 1)
edge_tail(const float* __restrict__ hw, const float* __restrict__ ef,
          const float* __restrict__ W1, const float* __restrict__ b1,
          float* __restrict__ out, int n, int e_base) {
    extern __shared__ __align__(1024) unsigned char smem[];
    const uint32_t smem_b = s2u(smem);
    const int tid = threadIdx.x;
    const int lane = tid & 31;
    const int wid = tid >> 5;          // 0..15
    const int nt = wid & 7;            // n16 group
    const int kh = wid >> 3;           // k-half (0: kt 0-3, 1: kt 4-7)
    const int e0 = e_base + blockIdx.x * 16;

    if (tid == 0) {
        #pragma unroll
        for (int i = 0; i < TSLOTS; ++i) {
            mbar_init(smem_b + MB_FULL(i), 1);
            mbar_init(smem_b + MB_EMPTY(i), 16);
        }
        asm volatile("fence.mbarrier_init.release.cluster;" ::: "memory");
    }
    __syncthreads();
    if (tid == 0) {
        #pragma unroll
        for (int i = 0; i < TSLOTS; ++i) {
            mbar_expect_tx(smem_b + MB_FULL(i), STEP_BYTES);
            bulk_g2s(smem_b + T_W2 + i * STEP_BYTES, g_w2h + (size_t)i * STEP_BYTES,
                     STEP_BYTES, smem_b + MB_FULL(i));
        }
    }

    // stage ef / W1 / b1
    {
        float* ef_s = (float*)(smem + T_EF);
        float* w1_s = (float*)(smem + T_W1);
        float* b1_s = (float*)(smem + T_B1);
        if (tid < 64) {
            int e = tid >> 2;
            float4 v = make_float4(0.f, 0.f, 0.f, 0.f);
            if (e0 + e < n) v = *(const float4*)(ef + (size_t)(e0 + e) * EDIM + (tid & 3) * 4);
            ((float4*)ef_s)[tid] = v;
        }
        ((float4*)w1_s)[tid] = ((const float4*)W1)[tid];
        if (tid < EH) b1_s[tid] = b1[tid];
    }
    __syncthreads();

    // MLP: 16 edges x 128 h, 4 h per thread
    {
        const float* ef_s = (const float*)(smem + T_EF);
        const float* w1_s = (const float*)(smem + T_W1);
        const float* b1_s = (const float*)(smem + T_B1);
        float* ht = (float*)(smem + T_HT);
        const int e = tid >> 5;          // 0..15
        const int part = tid & 31;       // 4 h each
        float efr[EDIM];
        #pragma unroll
        for (int k = 0; k < EDIM; ++k) efr[k] = ef_s[e * EDIM + k];
        const int h0 = part * 4;
        float4 acc4 = *(const float4*)(b1_s + h0);
        #pragma unroll
        for (int k = 0; k < EDIM; ++k) {
            float4 w = *(const float4*)(w1_s + k * EH + h0);
            acc4.x += efr[k] * w.x; acc4.y += efr[k] * w.y;
            acc4.z += efr[k] * w.z; acc4.w += efr[k] * w.w;
        }
        ht[(h0 + 0) * 16 + e] = fmaxf(acc4.x, 0.f);
        ht[(h0 + 1) * 16 + e] = fmaxf(acc4.y, 0.f);
        ht[(h0 + 2) * 16 + e] = fmaxf(acc4.z, 0.f);
        ht[(h0 + 3) * 16 + e] = fmaxf(acc4.w, 0.f);
        if (part == 0) ht[128 * 16 + e] = 1.0f;
    }
    __syncthreads();

    // hw fp16 image (16 rows, guarded)
    if (tid < 256) {
        int r = tid >> 4;
        int c = tid & 15;
        float4 a = make_float4(0.f, 0.f, 0.f, 0.f), b = a;
        if (e0 + r < n) {
            const float* s = hw + (size_t)(e0 + r) * DD + c * 8;
            a = *(const float4*)s;
            b = *(const float4*)(s + 4);
        }
        __half2 h0 = __floats2half2_rn(a.x, a.y);
        __half2 h1 = __floats2half2_rn(a.z, a.w);
        __half2 h2 = __floats2half2_rn(b.x, b.y);
        __half2 h3 = __floats2half2_rn(b.z, b.w);
        uint32_t off = (uint32_t)r * 256u + (swz_chunk((uint32_t)c, (uint32_t)(r & 7)) << 4);
        uint4 v;
        v.x = *(uint32_t*)&h0; v.y = *(uint32_t*)&h1;
        v.z = *(uint32_t*)&h2; v.w = *(uint32_t*)&h3;
        *(uint4*)(smem + T_HW + off) = v;
    }
    __syncthreads();

    const uint32_t rx = (uint32_t)(lane & 7);
    const uint32_t lhi = (uint32_t)(lane >> 4);
    uint32_t coffv[4];                 // this warp's 4 k-tiles
    #pragma unroll
    for (int kk = 0; kk < 4; ++kk)
        coffv[kk] = swz_chunk((uint32_t)((kh * 4 + kk) * 2) + lhi, rx) << 4;

    uint32_t A[4][4];
    {
        const uint32_t aBase = smem_b + T_HW + (uint32_t)(lane & 15) * 256u;
        #pragma unroll
        for (int kk = 0; kk < 4; ++kk)
            ldsm_x4(A[kk][0], A[kk][1], A[kk][2], A[kk][3], aBase + coffv[kk]);
    }
    const uint32_t bRow = (uint32_t)(nt * 16 + (lane & 15)) * 256u;
    const float* ht = (const float*)(smem + T_HT);
    const int quad = lane >> 2;

    float acc[2][4];
    #pragma unroll
    for (int f = 0; f < 2; ++f)
        #pragma unroll
        for (int q = 0; q < 4; ++q) acc[f][q] = 0.f;

    int slot = 0, use = 0;
    for (int s = 0; s < NSTEPS; ++s) {
        const uint32_t par = (uint32_t)use & 1u;
        mbar_wait(smem_b + MB_FULL(slot), par);

        const float hA = ht[s * 16 + quad];
        const float hB = ht[s * 16 + quad + 8];
        const uint32_t bSlot = smem_b + T_W2 + slot * STEP_BYTES;

        float d[2][4];
        #pragma unroll
        for (int kk = 0; kk < 4; ++kk) {
            uint32_t b0, b1r, b2, b3;
            ldsm_x4(b0, b1r, b2, b3, bSlot + bRow + coffv[kk]);
            if (kk == 0) {
                mma_zc(d[0], A[0], b0, b2);
                mma_zc(d[1], A[0], b1r, b3);
            } else {
                mma_acc(d[0], A[kk], b0, b2);
                mma_acc(d[1], A[kk], b1r, b3);
            }
        }
        __syncwarp();
        if (lane == 0) mbar_arrive(smem_b + MB_EMPTY(slot));

        #pragma unroll
        for (int f = 0; f < 2; ++f) {
            acc[f][0] += hA * d[f][0];  acc[f][1] += hA * d[f][1];
            acc[f][2] += hB * d[f][2];  acc[f][3] += hB * d[f][3];
        }

        if (tid == 0 && s + TSLOTS < NSTEPS) {
            mbar_wait(smem_b + MB_EMPTY(slot), par);
            mbar_expect_tx(smem_b + MB_FULL(slot), STEP_BYTES);
            bulk_g2s(smem_b + T_W2 + slot * STEP_BYTES,
                     g_w2h + (size_t)(s + TSLOTS) * STEP_BYTES, STEP_BYTES,
                     smem_b + MB_FULL(slot));
        }
        if (++slot == TSLOTS) { slot = 0; ++use; }
    }

    // -------- combine k-halves (smem, reusing Ht area) and write out --------
    float* cb = (float*)(smem + T_HT);     // 8 groups x 32 lanes x 8 floats = 8KB
    __syncthreads();                        // Ht reads done
    if (kh == 1) {
        float* dst = cb + (nt * 32 + lane) * 8;
        #pragma unroll
        for (int f = 0; f < 2; ++f)
            #pragma unroll
            for (int q = 0; q < 4; ++q) dst[f * 4 + q] = acc[f][q];
    }
    __syncthreads();
    if (kh == 0) {
        const float* src = cb + (nt * 32 + lane) * 8;
        #pragma unroll
        for (int f = 0; f < 2; ++f)
            #pragma unroll
            for (int q = 0; q < 4; ++q) acc[f][q] += src[f * 4 + q];

        const int er = e0 + quad;
        #pragma unroll
        for (int b = 0; b < 2; ++b) {
            const int col = nt * 16 + b * 8 + (lane & 3) * 2;
            if (er < n)
                *(float2*)(out + (size_t)er * DD + col) = make_float2(acc[b][0], acc[b][1]);
            if (er + 8 < n)
                *(float2*)(out + (size_t)(er + 8) * DD + col) = make_float2(acc[b][2], acc[b][3]);
        }
    }
}

// ---------------------------------------------------------------------------
extern "C" void kernel_launch(void* const* d_in, const int* in_sizes, int n_in,
                              void* d_out, int out_size) {
    const float* hw = (const float*)d_in[1];
    const float* ef = (const float*)d_in[2];
    const float* W1 = (const float*)d_in[3];
    const float* b1 = (const float*)d_in[4];
    const float* W2 = (const float*)d_in[5];
    const float* b2 = (const float*)d_in[6];
    const int n = in_sizes[1] / DD;

    w2_prepass<<<dim3(NSTEPS, 4), 128>>>(W2, b2);

    int full = n / 128;
    if (full > 148) full = 148;
    const int rem = n - full * 128;
    const int jobs = (rem + 15) / 16;
    if (jobs > 0) {
        cudaFuncSetAttribute(edge_tail, cudaFuncAttributeMaxDynamicSharedMemorySize,
                             TAIL_SMEM);
        edge_tail<<<jobs, 512, TAIL_SMEM>>>(hw, ef, W1, b1, (float*)d_out, n, full * 128);
    }
    if (full > 0) {
        cudaFuncSetAttribute(edge_main, cudaFuncAttributeMaxDynamicSharedMemorySize,
                             SMEM_TOTAL);
        edge_main<<<full, 256, SMEM_TOTAL>>>(hw, ef, W1, b1, (float*)d_out, n);
    }
}

// round 11
// speedup vs baseline: 1.2437x; 1.1360x over previous
#include <cuda_runtime.h>
#include <cuda_fp16.h>
#include <stdint.h>

// ---------------------------------------------------------------------------
// EdgeNetwork: messages_e = sum_h H[e,h]*(hw_e @ W2[h]^T) + (hw_e @ b2-tile)
// Single fused kernel: 148 CTAs x 128 edges (8 warps m32n64, R8 config at the
// legacy-HMMA ceiling). Leftover 1056 edges folded in as 132 chunks of
// (16 edges x 64 cols); CTA cid<132 owns chunk cid, processed by warps 0-3
// (one per SMSP) inside the SAME 129-step loop, sharing the W2 smem tile.
// ---------------------------------------------------------------------------

#define DD        128
#define EDIM      16
#define EH        128
#define NSTEPS    129
#define STEP_BYTES 32768
#define SLOTS     3

// ---- smem layout ----
#define MB_FULL(i)  ((i)*8)
#define MB_EMPTY(i) (32 + (i)*8)
#define HW_OFF      1024                 // 144 x 256B = 36864 -> ends 37888
#define HT_OFF      37888                // 129*128*4 = 66048 -> ends 103936
#define HTX_OFF     103936               // 129*16*4 = 8256 -> ends 112192
#define W2_OFF      112640               // 3 x 32768 -> ends 210944
#define SMEM_TOTAL  210944
// prologue scratch (inside HW region, dead before hw image build)
#define SCR_EF      1024                 // 128x16 f32
#define SCR_W1      9216                 // 16x128 f32
#define SCR_B1      17408                // 128 f32
#define SCR_EFX     17920                // 16x16 f32

static __device__ __align__(128) unsigned char g_w2h[(size_t)NSTEPS * STEP_BYTES];

__device__ __forceinline__ uint32_t s2u(const void* p) {
    return (uint32_t)__cvta_generic_to_shared(p);
}
__device__ __forceinline__ uint32_t swz_chunk(uint32_t c, uint32_t r7) {
    return (c & 8u) | ((c & 7u) ^ r7);
}
__device__ __forceinline__ void mbar_init(uint32_t a, uint32_t cnt) {
    asm volatile("mbarrier.init.shared.b64 [%0], %1;" :: "r"(a), "r"(cnt) : "memory");
}
__device__ __forceinline__ void mbar_expect_tx(uint32_t a, uint32_t bytes) {
    asm volatile("mbarrier.arrive.expect_tx.shared.b64 _, [%0], %1;"
                 :: "r"(a), "r"(bytes) : "memory");
}
__device__ __forceinline__ void mbar_arrive(uint32_t a) {
    asm volatile("mbarrier.arrive.shared.b64 _, [%0];" :: "r"(a) : "memory");
}
__device__ __forceinline__ void mbar_wait(uint32_t a, uint32_t parity) {
    asm volatile(
        "{\n\t.reg .pred P;\n\t"
        "W_%=:\n\t"
        "mbarrier.try_wait.parity.shared.b64 P, [%0], %1;\n\t"
        "@P bra.uni D_%=;\n\t"
        "bra.uni W_%=;\n\t"
        "D_%=:\n\t}"
        :: "r"(a), "r"(parity) : "memory");
}
__device__ __forceinline__ void bulk_g2s(uint32_t dst, const void* src, uint32_t bytes,
                                         uint32_t mbar) {
    asm volatile(
        "cp.async.bulk.shared::cluster.global.mbarrier::complete_tx::bytes [%0], [%1], %2, [%3];"
        :: "r"(dst), "l"(src), "r"(bytes), "r"(mbar) : "memory");
}
__device__ __forceinline__ void ldsm_x4(uint32_t& r0, uint32_t& r1, uint32_t& r2, uint32_t& r3,
                                        uint32_t addr) {
    asm volatile("ldmatrix.sync.aligned.m8n8.x4.shared.b16 {%0,%1,%2,%3}, [%4];"
                 : "=r"(r0), "=r"(r1), "=r"(r2), "=r"(r3) : "r"(addr));
}
__device__ __forceinline__ void mma_acc(float* c, const uint32_t* a,
                                        uint32_t b0, uint32_t b1) {
    asm volatile(
        "mma.sync.aligned.m16n8k16.row.col.f32.f16.f16.f32 "
        "{%0,%1,%2,%3}, {%4,%5,%6,%7}, {%8,%9}, {%0,%1,%2,%3};"
        : "+f"(c[0]), "+f"(c[1]), "+f"(c[2]), "+f"(c[3])
        : "r"(a[0]), "r"(a[1]), "r"(a[2]), "r"(a[3]), "r"(b0), "r"(b1));
}
__device__ __forceinline__ void mma_zc(float* d, const uint32_t* a,
                                       uint32_t b0, uint32_t b1) {
    asm volatile(
        "mma.sync.aligned.m16n8k16.row.col.f32.f16.f16.f32 "
        "{%0,%1,%2,%3}, {%4,%5,%6,%7}, {%8,%9}, {%10,%11,%12,%13};"
        : "=f"(d[0]), "=f"(d[1]), "=f"(d[2]), "=f"(d[3])
        : "r"(a[0]), "r"(a[1]), "r"(a[2]), "r"(a[3]), "r"(b0), "r"(b1),
          "f"(0.f), "f"(0.f), "f"(0.f), "f"(0.f));
}

// ---------------------------------------------------------------------------
__global__ void __launch_bounds__(128) w2_prepass(const float* __restrict__ W2,
                                                  const float* __restrict__ b2) {
    const int h = blockIdx.x;
    const int q = blockIdx.y;
    const int tid = threadIdx.x;
    const float* src = (h < EH) ? (W2 + (size_t)h * (DD * DD)) : b2;
    unsigned char* dst = g_w2h + (size_t)h * STEP_BYTES;
    #pragma unroll
    for (int it = 0; it < 4; ++it) {
        int cid = q * 512 + it * 128 + tid;
        int i = cid >> 4;
        int c = cid & 15;
        const float* s = src + (size_t)i * DD + c * 8;
        float4 a = *(const float4*)s;
        float4 b = *(const float4*)(s + 4);
        __half2 h0 = __floats2half2_rn(a.x, a.y);
        __half2 h1 = __floats2half2_rn(a.z, a.w);
        __half2 h2 = __floats2half2_rn(b.x, b.y);
        __half2 h3 = __floats2half2_rn(b.z, b.w);
        uint32_t off = (uint32_t)i * 256u + (swz_chunk((uint32_t)c, (uint32_t)(i & 7)) << 4);
        uint4 v;
        v.x = *(uint32_t*)&h0; v.y = *(uint32_t*)&h1;
        v.z = *(uint32_t*)&h2; v.w = *(uint32_t*)&h3;
        *(uint4*)(dst + off) = v;
    }
}

// ---------------------------------------------------------------------------
// Fused main: 128 edges/CTA + optional 16x64 extra chunk.
// 256 threads, 8 warps 4(M)x2(N) -> m32 x n64.
// ---------------------------------------------------------------------------
__global__ void __launch_bounds__(256, 1)
edge_main(const float* __restrict__ hw, const float* __restrict__ ef,
          const float* __restrict__ W1, const float* __restrict__ b1,
          float* __restrict__ out, int n, int exbase, int nchunks) {
    extern __shared__ __align__(1024) unsigned char smem[];
    const uint32_t smem_b = s2u(smem);
    const int tid = threadIdx.x;
    const int lane = tid & 31;
    const int wid = tid >> 5;
    const int warp_m = wid & 3;
    const int warp_n = wid >> 2;
    const int e0 = blockIdx.x * 128;

    const int cid = blockIdx.x;
    const bool ctaChunk = (cid < nchunks);
    const int xgrp = cid >> 1;            // 16-edge group
    const int xcolh = cid & 1;            // 64-col half
    const int eX0 = exbase + xgrp * 16;
    const bool warpChunk = ctaChunk && (wid < 4);

    if (tid == 0) {
        #pragma unroll
        for (int i = 0; i < SLOTS; ++i) {
            mbar_init(smem_b + MB_FULL(i), 1);
            mbar_init(smem_b + MB_EMPTY(i), 8);
        }
        asm volatile("fence.mbarrier_init.release.cluster;" ::: "memory");
    }
    __syncthreads();
    if (tid == 0) {
        #pragma unroll
        for (int i = 0; i < SLOTS; ++i) {
            mbar_expect_tx(smem_b + MB_FULL(i), STEP_BYTES);
            bulk_g2s(smem_b + W2_OFF + i * STEP_BYTES, g_w2h + (size_t)i * STEP_BYTES,
                     STEP_BYTES, smem_b + MB_FULL(i));
        }
    }

    // -------- stage ef / W1 / b1 / ef_x --------
    {
        float* ef_s = (float*)(smem + SCR_EF);
        float* w1_s = (float*)(smem + SCR_W1);
        float* b1_s = (float*)(smem + SCR_B1);
        float* efx_s = (float*)(smem + SCR_EFX);
        ((float4*)ef_s)[tid] = ((const float4*)(ef + (size_t)e0 * EDIM))[tid];
        ((float4*)ef_s)[tid + 256] = ((const float4*)(ef + (size_t)e0 * EDIM))[tid + 256];
        ((float4*)w1_s)[tid] = ((const float4*)W1)[tid];
        ((float4*)w1_s)[tid + 256] = ((const float4*)W1)[tid + 256];
        if (tid < EH) b1_s[tid] = b1[tid];
        if (tid < 64) {
            int e = tid >> 2;
            float4 v = make_float4(0.f, 0.f, 0.f, 0.f);
            if (ctaChunk && eX0 + e < n)
                v = *(const float4*)(ef + (size_t)(eX0 + e) * EDIM + (tid & 3) * 4);
            ((float4*)efx_s)[tid] = v;
        }
    }
    __syncthreads();

    // -------- MLP: Ht[h][e] fp32 (main 128 edges), step 128 = 1.0 --------
    {
        const float* ef_s = (const float*)(smem + SCR_EF);
        const float* w1_s = (const float*)(smem + SCR_W1);
        const float* b1_s = (const float*)(smem + SCR_B1);
        float* ht = (float*)(smem + HT_OFF);
        const int e = tid >> 1;
        const int part = tid & 1;
        float efr[EDIM];
        #pragma unroll
        for (int k = 0; k < EDIM; ++k) efr[k] = ef_s[e * EDIM + k];
        const int h0 = part * 64;
        #pragma unroll 4
        for (int hh = 0; hh < 64; hh += 4) {
            float4 acc4 = *(const float4*)(b1_s + h0 + hh);
            #pragma unroll
            for (int k = 0; k < EDIM; ++k) {
                float4 w = *(const float4*)(w1_s + k * EH + h0 + hh);
                acc4.x += efr[k] * w.x; acc4.y += efr[k] * w.y;
                acc4.z += efr[k] * w.z; acc4.w += efr[k] * w.w;
            }
            ht[(h0 + hh + 0) * 128 + e] = fmaxf(acc4.x, 0.f);
            ht[(h0 + hh + 1) * 128 + e] = fmaxf(acc4.y, 0.f);
            ht[(h0 + hh + 2) * 128 + e] = fmaxf(acc4.z, 0.f);
            ht[(h0 + hh + 3) * 128 + e] = fmaxf(acc4.w, 0.f);
        }
        if (part == 0) ht[128 * 128 + e] = 1.0f;
    }

    // -------- MLP for extra 16 edges: Htx[h][e] --------
    if (ctaChunk) {
        const float* efx_s = (const float*)(smem + SCR_EFX);
        const float* w1_s = (const float*)(smem + SCR_W1);
        const float* b1_s = (const float*)(smem + SCR_B1);
        float* htx = (float*)(smem + HTX_OFF);
        const int e = tid >> 4;          // 0..15
        const int part = tid & 15;       // 8 h each
        float efr[EDIM];
        #pragma unroll
        for (int k = 0; k < EDIM; ++k) efr[k] = efx_s[e * EDIM + k];
        const int h0 = part * 8;
        #pragma unroll
        for (int hh = 0; hh < 8; hh += 4) {
            float4 acc4 = *(const float4*)(b1_s + h0 + hh);
            #pragma unroll
            for (int k = 0; k < EDIM; ++k) {
                float4 w = *(const float4*)(w1_s + k * EH + h0 + hh);
                acc4.x += efr[k] * w.x; acc4.y += efr[k] * w.y;
                acc4.z += efr[k] * w.z; acc4.w += efr[k] * w.w;
            }
            htx[(h0 + hh + 0) * 16 + e] = fmaxf(acc4.x, 0.f);
            htx[(h0 + hh + 1) * 16 + e] = fmaxf(acc4.y, 0.f);
            htx[(h0 + hh + 2) * 16 + e] = fmaxf(acc4.z, 0.f);
            htx[(h0 + hh + 3) * 16 + e] = fmaxf(acc4.w, 0.f);
        }
        if (part == 0) htx[128 * 16 + e] = 1.0f;
    }
    __syncthreads();

    // -------- hw fp16 image (main rows 0..127, extra rows 128..143) --------
    {
        #pragma unroll
        for (int q = 0; q < 8; ++q) {
            int cid2 = tid + q * 256;
            int r = cid2 >> 4;
            int c = cid2 & 15;
            const float* s = hw + (size_t)(e0 + r) * DD + c * 8;
            float4 a = *(const float4*)s;
            float4 b = *(const float4*)(s + 4);
            __half2 h0 = __floats2half2_rn(a.x, a.y);
            __half2 h1 = __floats2half2_rn(a.z, a.w);
            __half2 h2 = __floats2half2_rn(b.x, b.y);
            __half2 h3 = __floats2half2_rn(b.z, b.w);
            uint32_t off = (uint32_t)r * 256u + (swz_chunk((uint32_t)c, (uint32_t)(r & 7)) << 4);
            uint4 v;
            v.x = *(uint32_t*)&h0; v.y = *(uint32_t*)&h1;
            v.z = *(uint32_t*)&h2; v.w = *(uint32_t*)&h3;
            *(uint4*)(smem + HW_OFF + off) = v;
        }
        if (ctaChunk) {
            int r = tid >> 4;            // 0..15
            int c = tid & 15;
            float4 a = make_float4(0.f, 0.f, 0.f, 0.f), b = a;
            if (eX0 + r < n) {
                const float* s = hw + (size_t)(eX0 + r) * DD + c * 8;
                a = *(const float4*)s;
                b = *(const float4*)(s + 4);
            }
            __half2 h0 = __floats2half2_rn(a.x, a.y);
            __half2 h1 = __floats2half2_rn(a.z, a.w);
            __half2 h2 = __floats2half2_rn(b.x, b.y);
            __half2 h3 = __floats2half2_rn(b.z, b.w);
            int rr = 128 + r;
            uint32_t off = (uint32_t)rr * 256u + (swz_chunk((uint32_t)c, (uint32_t)(rr & 7)) << 4);
            uint4 v;
            v.x = *(uint32_t*)&h0; v.y = *(uint32_t*)&h1;
            v.z = *(uint32_t*)&h2; v.w = *(uint32_t*)&h3;
            *(uint4*)(smem + HW_OFF + off) = v;
        }
    }
    __syncthreads();

    // -------- A fragments into registers (step-invariant) --------
    const uint32_t rx = (uint32_t)(lane & 7);
    const uint32_t lhi = (uint32_t)(lane >> 4);
    uint32_t coffv[8];
    #pragma unroll
    for (int kt = 0; kt < 8; ++kt)
        coffv[kt] = swz_chunk((uint32_t)(kt * 2) + lhi, rx) << 4;

    uint32_t A0[8][4], A1[8][4];
    {
        const uint32_t aBase0 = smem_b + HW_OFF + (uint32_t)(warp_m * 32 + (lane & 15)) * 256u;
        const uint32_t aBase1 = aBase0 + 16u * 256u;
        #pragma unroll
        for (int kt = 0; kt < 8; ++kt) {
            ldsm_x4(A0[kt][0], A0[kt][1], A0[kt][2], A0[kt][3], aBase0 + coffv[kt]);
            ldsm_x4(A1[kt][0], A1[kt][1], A1[kt][2], A1[kt][3], aBase1 + coffv[kt]);
        }
    }

    uint32_t bR[4];
    #pragma unroll
    for (int g = 0; g < 4; ++g)
        bR[g] = (uint32_t)(warp_n * 64 + g * 16 + (lane & 15)) * 256u;

    // extra chunk addressing (warps 0-3): A rows 128+(lane&15); B cols = colh*64+wid*16
    const uint32_t aBaseX = smem_b + HW_OFF + (uint32_t)(128 + (lane & 15)) * 256u;
    const uint32_t bRX = (uint32_t)(xcolh * 64 + wid * 16 + (lane & 15)) * 256u;

    const float* ht = (const float*)(smem + HT_OFF);
    const float* htx = (const float*)(smem + HTX_OFF);
    const int quad = lane >> 2;
    const int hrow = warp_m * 32 + quad;

    float acc[2][8][4];
    #pragma unroll
    for (int mf = 0; mf < 2; ++mf)
        #pragma unroll
        for (int f = 0; f < 8; ++f)
            #pragma unroll
            for (int q = 0; q < 4; ++q) acc[mf][f][q] = 0.f;
    float accx[2][4];
    #pragma unroll
    for (int f = 0; f < 2; ++f)
        #pragma unroll
        for (int q = 0; q < 4; ++q) accx[f][q] = 0.f;

    // -------- main loop --------
    int slot = 0, use = 0;
    for (int s = 0; s < NSTEPS; ++s) {
        const uint32_t par = (uint32_t)use & 1u;
        mbar_wait(smem_b + MB_FULL(slot), par);

        const float hA0 = ht[s * 128 + hrow];
        const float hB0 = ht[s * 128 + hrow + 8];
        const float hA1 = ht[s * 128 + hrow + 16];
        const float hB1 = ht[s * 128 + hrow + 24];
        const uint32_t bSlot = smem_b + W2_OFF + slot * STEP_BYTES;

        float d[16][4];
        #pragma unroll
        for (int kt = 0; kt < 8; ++kt) {
            #pragma unroll
            for (int g = 0; g < 4; ++g) {
                uint32_t b0, b1r, b2, b3;
                ldsm_x4(b0, b1r, b2, b3, bSlot + bR[g] + coffv[kt]);
                if (kt == 0) {
                    mma_zc(d[g * 2 + 0], A0[0], b0, b2);
                    mma_zc(d[g * 2 + 1], A0[0], b1r, b3);
                    mma_zc(d[8 + g * 2 + 0], A1[0], b0, b2);
                    mma_zc(d[8 + g * 2 + 1], A1[0], b1r, b3);
                } else {
                    mma_acc(d[g * 2 + 0], A0[kt], b0, b2);
                    mma_acc(d[g * 2 + 1], A0[kt], b1r, b3);
                    mma_acc(d[8 + g * 2 + 0], A1[kt], b0, b2);
                    mma_acc(d[8 + g * 2 + 1], A1[kt], b1r, b3);
                }
            }
        }

        if (!warpChunk) {
            __syncwarp();
            if (lane == 0) mbar_arrive(smem_b + MB_EMPTY(slot));
        }

        // main scale into persistent accumulators
        #pragma unroll
        for (int j = 0; j < 8; ++j) {
            float* a0 = acc[0][j];
            float* a1 = acc[1][j];
            a0[0] += hA0 * d[j][0];      a0[1] += hA0 * d[j][1];
            a0[2] += hB0 * d[j][2];      a0[3] += hB0 * d[j][3];
            a1[0] += hA1 * d[8 + j][0];  a1[1] += hA1 * d[8 + j][1];
            a1[2] += hB1 * d[8 + j][2];  a1[3] += hB1 * d[8 + j][3];
        }

        // extra chunk (warps 0-3 of chunk-carrying CTAs)
        if (warpChunk) {
            const float hXA = htx[s * 16 + quad];
            const float hXB = htx[s * 16 + quad + 8];
            float dx[2][4];
            #pragma unroll
            for (int kt = 0; kt < 8; ++kt) {
                uint32_t ax0, ax1, ax2, ax3, b0, b1r, b2, b3;
                ldsm_x4(ax0, ax1, ax2, ax3, aBaseX + coffv[kt]);
                ldsm_x4(b0, b1r, b2, b3, bSlot + bRX + coffv[kt]);
                uint32_t ax[4] = {ax0, ax1, ax2, ax3};
                if (kt == 0) {
                    mma_zc(dx[0], ax, b0, b2);
                    mma_zc(dx[1], ax, b1r, b3);
                } else {
                    mma_acc(dx[0], ax, b0, b2);
                    mma_acc(dx[1], ax, b1r, b3);
                }
            }
            __syncwarp();
            if (lane == 0) mbar_arrive(smem_b + MB_EMPTY(slot));
            #pragma unroll
            for (int f = 0; f < 2; ++f) {
                accx[f][0] += hXA * dx[f][0];  accx[f][1] += hXA * dx[f][1];
                accx[f][2] += hXB * dx[f][2];  accx[f][3] += hXB * dx[f][3];
            }
        }

        if (tid == 0 && s + SLOTS < NSTEPS) {
            mbar_wait(smem_b + MB_EMPTY(slot), par);
            mbar_expect_tx(smem_b + MB_FULL(slot), STEP_BYTES);
            bulk_g2s(smem_b + W2_OFF + slot * STEP_BYTES,
                     g_w2h + (size_t)(s + SLOTS) * STEP_BYTES, STEP_BYTES,
                     smem_b + MB_FULL(slot));
        }
        if (++slot == SLOTS) { slot = 0; ++use; }
    }

    // -------- epilogue: main tile --------
    #pragma unroll
    for (int mf = 0; mf < 2; ++mf) {
        const int er = e0 + warp_m * 32 + mf * 16 + quad;
        #pragma unroll
        for (int gg = 0; gg < 4; ++gg)
            #pragma unroll
            for (int b = 0; b < 2; ++b) {
                const int f = gg * 2 + b;
                const int col = warp_n * 64 + gg * 16 + b * 8 + (lane & 3) * 2;
                *(float2*)(out + (size_t)er * DD + col) =
                    make_float2(acc[mf][f][0], acc[mf][f][1]);
                *(float2*)(out + (size_t)(er + 8) * DD + col) =
                    make_float2(acc[mf][f][2], acc[mf][f][3]);
            }
    }
    // -------- epilogue: extra chunk --------
    if (warpChunk) {
        const int er = eX0 + quad;
        #pragma unroll
        for (int b = 0; b < 2; ++b) {
            const int col = xcolh * 64 + wid * 16 + b * 8 + (lane & 3) * 2;
            if (er < n)
                *(float2*)(out + (size_t)er * DD + col) =
                    make_float2(accx[b][0], accx[b][1]);
            if (er + 8 < n)
                *(float2*)(out + (size_t)(er + 8) * DD + col) =
                    make_float2(accx[b][2], accx[b][3]);
        }
    }
}

// ---------------------------------------------------------------------------
extern "C" void kernel_launch(void* const* d_in, const int* in_sizes, int n_in,
                              void* d_out, int out_size) {
    const float* hw = (const float*)d_in[1];
    const float* ef = (const float*)d_in[2];
    const float* W1 = (const float*)d_in[3];
    const float* b1 = (const float*)d_in[4];
    const float* W2 = (const float*)d_in[5];
    const float* b2 = (const float*)d_in[6];
    const int n = in_sizes[1] / DD;

    w2_prepass<<<dim3(NSTEPS, 4), 128>>>(W2, b2);

    int full = n / 128;
    if (full > 148) full = 148;
    const int exbase = full * 128;
    const int rem = n - exbase;
    const int nchunks = ((rem + 15) / 16) * 2;   // (16e x 64c) chunks

    if (full > 0) {
        cudaFuncSetAttribute(edge_main, cudaFuncAttributeMaxDynamicSharedMemorySize,
                             SMEM_TOTAL);
        edge_main<<<full, 256, SMEM_TOTAL>>>(hw, ef, W1, b1, (float*)d_out, n,
                                             exbase, nchunks);
    }
}